// round 1
// baseline (speedup 1.0000x reference)
#include <cuda_runtime.h>
#include <math.h>

#define B 256
#define D 512
#define S 196

// Scratch for w[b,d] = memory[b,d]*v[b,d] + u[b,d]  (device global: no allocs allowed)
__device__ float g_w[B * D];

// ---------------------------------------------------------------------------
// Kernel 1: w[b,d] = memory[b,d] * (sum_e u[b,e]*W[e,d]) + ctrl[b,d]*w_attn[d]
//   u[b,e] = ctrl[b,e]*w_attn[e]
// Grid: (d_tiles=4, b_tiles=32), 128 threads. Each CTA: 8 batches x 128 d-cols.
// ---------------------------------------------------------------------------
__global__ __launch_bounds__(128) void prep_kernel(
    const float* __restrict__ memory,
    const float* __restrict__ ctrl,
    const float* __restrict__ W,       // [e, d] row-major (d contiguous)
    const float* __restrict__ w_attn)
{
    const int d  = blockIdx.x * 128 + threadIdx.x;
    const int b0 = blockIdx.y * 8;

    __shared__ float u_s[D * 8];   // u_s[e*8 + j] = ctrl[b0+j, e] * w_attn[e]

    for (int idx = threadIdx.x; idx < D * 8; idx += 128) {
        int e = idx >> 3;
        int j = idx & 7;
        u_s[idx] = ctrl[(b0 + j) * D + e] * w_attn[e];
    }
    __syncthreads();

    float acc[8];
#pragma unroll
    for (int j = 0; j < 8; j++) acc[j] = 0.f;

#pragma unroll 8
    for (int e = 0; e < D; e++) {
        float wv = W[e * D + d];                       // coalesced across threads
        const float4 ua = *reinterpret_cast<const float4*>(&u_s[e * 8]);
        const float4 ub = *reinterpret_cast<const float4*>(&u_s[e * 8 + 4]);
        acc[0] += wv * ua.x;  acc[1] += wv * ua.y;
        acc[2] += wv * ua.z;  acc[3] += wv * ua.w;
        acc[4] += wv * ub.x;  acc[5] += wv * ub.y;
        acc[6] += wv * ub.z;  acc[7] += wv * ub.w;
    }

    const float wa = w_attn[d];
#pragma unroll
    for (int j = 0; j < 8; j++) {
        int b = b0 + j;
        g_w[b * D + d] = memory[b * D + d] * acc[j] + ctrl[b * D + d] * wa;
    }
}

// ---------------------------------------------------------------------------
// Kernel 2: per-batch logits + softmax + weighted sum.
//   rai[s]  = sum_d w[b,d] * kb[b,d,s]
//   rvi     = softmax_s(rai)
//   out[e]  = sum_s rvi[s] * kb[b,e,s]
// One CTA per batch, 512 threads (16 warps). Warp-per-row streaming in both
// passes -> fully coalesced 128B warp loads over the contiguous s-axis.
// ---------------------------------------------------------------------------
__global__ __launch_bounds__(512) void read_unit_kernel(
    const float* __restrict__ kb,     // [B, D, S]
    float* __restrict__ out)          // [B, D]
{
    const int b    = blockIdx.x;
    const int tid  = threadIdx.x;
    const int wid  = tid >> 5;
    const int lane = tid & 31;

    __shared__ float w_s[D];
    __shared__ float part[16][200];   // per-warp partial rai (stride-padded)
    __shared__ float rvi_s[200];
    __shared__ float red[32];

    const float* __restrict__ kbb = kb + (size_t)b * (D * S);

    // load w[b, :]
    if (tid < D) w_s[tid] = g_w[b * D + tid];
    __syncthreads();

    // ---- Pass A: rai[s] = sum_d w[d] * kb[d][s] ----
    float acc[7];
#pragma unroll
    for (int c = 0; c < 7; c++) acc[c] = 0.f;

#pragma unroll 4
    for (int d = wid; d < D; d += 16) {
        const float wv = w_s[d];
        const float* __restrict__ row = kbb + d * S;
#pragma unroll
        for (int c = 0; c < 6; c++)
            acc[c] += wv * row[c * 32 + lane];
        if (lane < 4)
            acc[6] += wv * row[192 + lane];
    }
#pragma unroll
    for (int c = 0; c < 7; c++) {
        int s = c * 32 + lane;
        if (s < S) part[wid][s] = acc[c];
    }
    __syncthreads();

    // deterministic cross-warp reduction of partials
    float rai = -INFINITY;
    if (tid < S) {
        float sum = 0.f;
#pragma unroll
        for (int k = 0; k < 16; k++) sum += part[k][tid];
        rai = sum;
    }

    // ---- softmax over s (block reduce max, then sum) ----
    float m = rai;
#pragma unroll
    for (int off = 16; off > 0; off >>= 1)
        m = fmaxf(m, __shfl_xor_sync(0xffffffff, m, off));
    if (lane == 0) red[wid] = m;
    __syncthreads();
    if (wid == 0) {
        float v = (lane < 16) ? red[lane] : -INFINITY;
#pragma unroll
        for (int off = 16; off > 0; off >>= 1)
            v = fmaxf(v, __shfl_xor_sync(0xffffffff, v, off));
        if (lane == 0) red[0] = v;
    }
    __syncthreads();
    const float gmax = red[0];
    __syncthreads();

    float p = (tid < S) ? expf(rai - gmax) : 0.f;
    float sacc = p;
#pragma unroll
    for (int off = 16; off > 0; off >>= 1)
        sacc += __shfl_xor_sync(0xffffffff, sacc, off);
    if (lane == 0) red[wid] = sacc;
    __syncthreads();
    if (wid == 0) {
        float v = (lane < 16) ? red[lane] : 0.f;
#pragma unroll
        for (int off = 16; off > 0; off >>= 1)
            v += __shfl_xor_sync(0xffffffff, v, off);
        if (lane == 0) red[0] = v;
    }
    __syncthreads();
    const float inv_sum = 1.f / red[0];
    if (tid < S) rvi_s[tid] = p * inv_sum;
    __syncthreads();

    // ---- Pass B: out[e] = sum_s rvi[s] * kb[e][s] ----
#pragma unroll 2
    for (int e = wid; e < D; e += 16) {
        const float* __restrict__ row = kbb + e * S;
        float sum = 0.f;
#pragma unroll
        for (int c = 0; c < 6; c++)
            sum += row[c * 32 + lane] * rvi_s[c * 32 + lane];
        if (lane < 4)
            sum += row[192 + lane] * rvi_s[192 + lane];
#pragma unroll
        for (int off = 16; off > 0; off >>= 1)
            sum += __shfl_xor_sync(0xffffffff, sum, off);
        if (lane == 0) out[b * D + e] = sum;
    }
}

extern "C" void kernel_launch(void* const* d_in, const int* in_sizes, int n_in,
                              void* d_out, int out_size)
{
    const float* memory = (const float*)d_in[0];  // [B, D]
    const float* ctrl   = (const float*)d_in[1];  // [B, D]
    const float* kb     = (const float*)d_in[2];  // [B, D, S]
    const float* W      = (const float*)d_in[3];  // [D, D]
    // d_in[4] = b_concat: constant shift inside softmax -> drops out, unused
    const float* w_attn = (const float*)d_in[5];  // [D]
    float* out = (float*)d_out;                   // [B, D]

    prep_kernel<<<dim3(4, 32), 128>>>(memory, ctrl, W, w_attn);
    read_unit_kernel<<<B, 512>>>(kb, out);
}